// round 14
// baseline (speedup 1.0000x reference)
#include <cuda_runtime.h>
#include <cuda_bf16.h>
#include <stdint.h>

#define BSZ 8
#define NN 2048
#define HH 512
#define M_TOT (BSZ*NN)

// ---------------- scratch (device globals; allocation-free) ----------------
__device__ __nv_bfloat16 g_featsb[BSZ*NN*HH];   // feats in bf16
__device__ __nv_bfloat16 g_wb[HH*HH];           // fc_w in bf16  [o][h]
__device__ __nv_bfloat16 g_fpb[BSZ*NN*HH];      // feat_proj in bf16
__device__ float g_qacc[M_TOT], g_kacc[M_TOT];  // atomic partial dots
__device__ __align__(16) float g_qv[M_TOT];
__device__ __align__(16) float g_Eq[M_TOT];
__device__ __align__(16) float g_eq[M_TOT];
__device__ __align__(16) float g_kv[M_TOT];
__device__ __align__(16) float g_Ek[M_TOT];
__device__ __align__(16) float g_ek[M_TOT];

// ---------------- PTX helpers ----------------
__device__ __forceinline__ uint32_t smem_u32(const void* p){
  return (uint32_t)__cvta_generic_to_shared(p);
}
__device__ __forceinline__ void cp_async16(void* s, const void* g){
  asm volatile("cp.async.cg.shared.global [%0], [%1], 16;\n" :: "r"(smem_u32(s)), "l"(g));
}
__device__ __forceinline__ void cp_commit(){ asm volatile("cp.async.commit_group;\n"); }
template<int NG> __device__ __forceinline__ void cp_wait(){
  asm volatile("cp.async.wait_group %0;\n" :: "n"(NG));
}
__device__ __forceinline__ void ldsm4(uint32_t* r, const void* p){
  asm volatile("ldmatrix.sync.aligned.m8n8.x4.shared.b16 {%0,%1,%2,%3}, [%4];\n"
    : "=r"(r[0]),"=r"(r[1]),"=r"(r[2]),"=r"(r[3]) : "r"(smem_u32(p)));
}
__device__ __forceinline__ void ldsm4t(uint32_t* r, const void* p){
  asm volatile("ldmatrix.sync.aligned.m8n8.x4.trans.shared.b16 {%0,%1,%2,%3}, [%4];\n"
    : "=r"(r[0]),"=r"(r[1]),"=r"(r[2]),"=r"(r[3]) : "r"(smem_u32(p)));
}
__device__ __forceinline__ void mma16816(float* c, const uint32_t* a, const uint32_t* b){
  asm volatile("mma.sync.aligned.m16n8k16.row.col.f32.bf16.bf16.f32 "
    "{%0,%1,%2,%3}, {%4,%5,%6,%7}, {%8,%9}, {%0,%1,%2,%3};\n"
    : "+f"(c[0]),"+f"(c[1]),"+f"(c[2]),"+f"(c[3])
    : "r"(a[0]),"r"(a[1]),"r"(a[2]),"r"(a[3]), "r"(b[0]),"r"(b[1]));
}

// ---------------- K0: merged converts (feats->bf16, fc_w->bf16, zero q/k acc) ----------------
#define N4F (BSZ*NN*HH/4)
#define N4W (HH*HH/4)
__global__ void cvt_all_kernel(const float* __restrict__ feats, const float* __restrict__ fc_w){
  int i = blockIdx.x*blockDim.x + threadIdx.x;
  if (i < N4F){
    float4 v = reinterpret_cast<const float4*>(feats)[i];
    reinterpret_cast<__nv_bfloat162*>(g_featsb)[i*2+0] = __floats2bfloat162_rn(v.x, v.y);
    reinterpret_cast<__nv_bfloat162*>(g_featsb)[i*2+1] = __floats2bfloat162_rn(v.z, v.w);
  }
  if (i < N4W){
    float4 v = reinterpret_cast<const float4*>(fc_w)[i];
    reinterpret_cast<__nv_bfloat162*>(g_wb)[i*2+0] = __floats2bfloat162_rn(v.x, v.y);
    reinterpret_cast<__nv_bfloat162*>(g_wb)[i*2+1] = __floats2bfloat162_rn(v.z, v.w);
  }
  if (i < M_TOT){ g_qacc[i] = 0.f; g_kacc[i] = 0.f; }
}

// ---------------- K1: feat_proj GEMM + fused q/k partial dots ----------------
__global__ __launch_bounds__(256) void fc_gemm_kernel(const float* __restrict__ fc_b,
                                                      const float* __restrict__ qw_,
                                                      const float* __restrict__ kw_){
  __shared__ __nv_bfloat16 As[2][128][40];
  __shared__ __nv_bfloat16 Bs[2][128][40];
  const int tid = threadIdx.x, lane = tid & 31, warp = tid >> 5;
  const int m0 = blockIdx.y*128, n0 = blockIdx.x*128;
  const int wm = warp >> 1, wn = warp & 1;
  const int m_off = wm*32, n_off = wn*64;

  float c[2][8][4];
  #pragma unroll
  for (int a=0;a<2;a++) for (int b=0;b<8;b++) for (int d=0;d<4;d++) c[a][b][d]=0.f;

  auto load_chunk = [&](int kc, int buf){
    int k0 = kc*32;
    #pragma unroll
    for (int s2=0;s2<2;s2++){
      int s = tid + s2*256;
      int row = s >> 2, c8 = (s & 3) << 3;
      cp_async16(&As[buf][row][c8], g_featsb + (size_t)(m0+row)*HH + k0 + c8);
      cp_async16(&Bs[buf][row][c8], g_wb     + (size_t)(n0+row)*HH + k0 + c8);
    }
    cp_commit();
  };

  load_chunk(0,0);
  for (int kc=0;kc<16;kc++){
    if (kc+1<16) { load_chunk(kc+1,(kc+1)&1); cp_wait<1>(); }
    else         { cp_wait<0>(); }
    __syncthreads();
    const int cur = kc & 1;
    #pragma unroll
    for (int ks=0;ks<2;ks++){
      uint32_t a[2][4];
      #pragma unroll
      for (int mf=0;mf<2;mf++)
        ldsm4(a[mf], &As[cur][m_off + mf*16 + (lane&15)][ks*16 + ((lane>>4)<<3)]);
      uint32_t bb[8][2];
      #pragma unroll
      for (int nf2=0;nf2<4;nf2++){
        uint32_t t[4];
        int nl = n_off + nf2*16 + (lane&7) + (((lane>>4)&1)<<3);
        int kl = ks*16 + (((lane>>3)&1)<<3);
        ldsm4(t, &Bs[cur][nl][kl]);
        bb[nf2*2+0][0]=t[0]; bb[nf2*2+0][1]=t[1];
        bb[nf2*2+1][0]=t[2]; bb[nf2*2+1][1]=t[3];
      }
      #pragma unroll
      for (int mf=0;mf<2;mf++)
        #pragma unroll
        for (int nf=0;nf<8;nf++)
          mma16816(c[mf][nf], a[mf], bb[nf]);
    }
    __syncthreads();
  }
  // epilogue: +bias, store bf16, accumulate q/k partial dots
  float qp[2][2] = {{0.f,0.f},{0.f,0.f}};
  float kp[2][2] = {{0.f,0.f},{0.f,0.f}};
  #pragma unroll
  for (int mf=0;mf<2;mf++){
    #pragma unroll
    for (int nf=0;nf<8;nf++){
      int col = n0 + n_off + nf*8 + ((lane&3)<<1);
      float b0 = __ldg(&fc_b[col]), b1 = __ldg(&fc_b[col+1]);
      float qw0 = __ldg(&qw_[col]), qw1 = __ldg(&qw_[col+1]);
      float kw0 = __ldg(&kw_[col]), kw1 = __ldg(&kw_[col+1]);
      #pragma unroll
      for (int rr=0;rr<2;rr++){
        int row = m0 + m_off + mf*16 + (lane>>2) + rr*8;
        float v0 = c[mf][nf][rr*2+0] + b0;
        float v1 = c[mf][nf][rr*2+1] + b1;
        *reinterpret_cast<__nv_bfloat162*>(&g_fpb[(size_t)row*HH + col]) =
            __floats2bfloat162_rn(v0, v1);
        qp[mf][rr] += v0*qw0 + v1*qw1;
        kp[mf][rr] += v0*kw0 + v1*kw1;
      }
    }
  }
  #pragma unroll
  for (int mf=0;mf<2;mf++){
    #pragma unroll
    for (int rr=0;rr<2;rr++){
      float q = qp[mf][rr], k = kp[mf][rr];
      q += __shfl_xor_sync(0xffffffffu, q, 1);
      q += __shfl_xor_sync(0xffffffffu, q, 2);
      k += __shfl_xor_sync(0xffffffffu, k, 1);
      k += __shfl_xor_sync(0xffffffffu, k, 2);
      if ((lane & 3) == 0){
        int row = m0 + m_off + mf*16 + (lane>>2) + rr*8;
        atomicAdd(&g_qacc[row], q);
        atomicAdd(&g_kacc[row], k);
      }
    }
  }
}

// ---------------- K2: finalize q/k + exp precompute ----------------
__global__ void qk_fin_kernel(const float* __restrict__ qb, const float* __restrict__ kb){
  int i = blockIdx.x*blockDim.x + threadIdx.x;
  if (i < M_TOT){
    float q = g_qacc[i] + __ldg(qb);
    float k = g_kacc[i] + __ldg(kb);
    g_qv[i]=q; g_Eq[i]=expf(q); g_eq[i]=expf(0.01f*q);
    g_kv[i]=k; g_Ek[i]=expf(k); g_ek[i]=expf(0.01f*k);
  }
}

// ---------------- K3: warp-specialized attention + residual ----------------
// 576 threads = 16 MMA warps (identical layout to the 170us R8 kernel) + 2 producer warps.
// Producers: adj cp.async + wcompute(jt+1) + Z, concurrent with consumers' MMA(jt).
// Consumers: fp cp.async (jt+1) + MMA(jt). One __syncthreads per iteration.
#define TJ 64
#define NT (NN/TJ)
#define FPS 520   // fp tile stride (bf16)
#define WSS 72    // w tile stride (bf16): 64 + 8 pad
#define ADJS 68   // adj row stride (f32): 64 + 4 pad
#define NTHR 576
#define SMEM_K3 (2*TJ*FPS*2 + 2*64*WSS*2 + 64*ADJS*4 + 64*4)

__global__ __launch_bounds__(NTHR,1) void attn_kernel(const float* __restrict__ adj,
                                                      const float* __restrict__ feats,
                                                      float* __restrict__ out){
  extern __shared__ char smraw[];
  __nv_bfloat16* fps = (__nv_bfloat16*)smraw;                          // [2][64][520]
  __nv_bfloat16* ws  = (__nv_bfloat16*)(smraw + 2*TJ*FPS*2);           // [2][64][72]
  float* adjs = (float*)(smraw + 2*TJ*FPS*2 + 2*64*WSS*2);             // [64][68]
  float* zs   = (float*)(smraw + 2*TJ*FPS*2 + 2*64*WSS*2 + 64*ADJS*4); // [64]

  const int tid = threadIdx.x, lane = tid & 31, warp = tid >> 5;
  const int b  = blockIdx.y;
  const int i0 = blockIdx.x*64;
  const int base = b*NN;
  const bool is_mma = (tid < 512);

  // ---------- producer state (warps 16,17; thread pt owns row pt) ----------
  const int pt = tid - 512;            // 0..63 for producers
  float qi=0.f, Eqi=0.f, eqi=0.f, zp=0.f;
  if (!is_mma){
    qi  = __ldg(g_qv + base + i0 + pt);
    Eqi = __ldg(g_Eq + base + i0 + pt);
    eqi = __ldg(g_eq + base + i0 + pt);
  }

  auto load_adj = [&](int jt){
    // producer thread pt: its 64-col adj row = 16 x 16B chunks
    const float* src = adj + (size_t)(base + i0 + pt)*NN + jt*TJ;
    float* dst = &adjs[pt*ADJS];
    #pragma unroll
    for (int g=0; g<16; g++) cp_async16(dst + g*4, src + g*4);
    cp_commit();
  };
  auto wcompute = [&](int jt, int buf){
    // row pt, 64 cols
    __nv_bfloat16* wrow = &ws[(size_t)buf*64*WSS + pt*WSS];
    const float* arow = &adjs[pt*ADJS];
    #pragma unroll
    for (int g=0; g<16; g++){
      int jj = g*4;
      int jg = base + jt*TJ + jj;
      float4 a4 = *reinterpret_cast<const float4*>(arow + jj);
      float4 k4 = __ldg(reinterpret_cast<const float4*>(g_kv + jg));
      float4 E4 = __ldg(reinterpret_cast<const float4*>(g_Ek + jg));
      float4 e4 = __ldg(reinterpret_cast<const float4*>(g_ek + jg));
      float w0 = a4.x * ((qi + k4.x >= 0.f) ? Eqi*E4.x : eqi*e4.x);
      float w1 = a4.y * ((qi + k4.y >= 0.f) ? Eqi*E4.y : eqi*e4.y);
      float w2 = a4.z * ((qi + k4.z >= 0.f) ? Eqi*E4.z : eqi*e4.z);
      float w3 = a4.w * ((qi + k4.w >= 0.f) ? Eqi*E4.w : eqi*e4.w);
      zp += (w0 + w1) + (w2 + w3);
      *reinterpret_cast<__nv_bfloat162*>(wrow + jj + 0) = __floats2bfloat162_rn(w0, w1);
      *reinterpret_cast<__nv_bfloat162*>(wrow + jj + 2) = __floats2bfloat162_rn(w2, w3);
    }
  };
  auto load_fp = [&](int jt, int buf){
    // consumers: TJ x 512 bf16 = 64KB, 8 x 16B chunks per thread (512 threads)
    const __nv_bfloat16* src = g_fpb + (size_t)(base + jt*TJ)*HH;
    #pragma unroll
    for (int s=0;s<8;s++){
      int seg = tid + s*512;
      int row = seg >> 6, hs = (seg & 63) << 3;
      cp_async16(&fps[(size_t)buf*TJ*FPS + row*FPS + hs], src + (size_t)row*HH + hs);
    }
    cp_commit();
  };

  float c[2][8][4];
  #pragma unroll
  for (int a=0;a<2;a++) for (int nb=0;nb<8;nb++) for (int d=0;d<4;d++) c[a][nb][d]=0.f;
  const int wm = warp >> 3, wn = warp & 7;   // for MMA warps only (warp<16)
  const int iw = wm*32, hw = wn*64;

  // ---- prologue: fp(0) by consumers, adj(0)+w(0) by producers ----
  if (is_mma){
    load_fp(0,0);
    cp_wait<0>();
  } else {
    load_adj(0);
    cp_wait<0>();
    wcompute(0,0);                 // ws[0]
  }
  __syncthreads();                 // fp(0) + ws(0) visible to all

  // ---- main loop: one barrier per iteration ----
  for (int jt=0; jt<NT; jt++){
    const int buf = jt & 1;
    const bool more = (jt+1 < NT);

    if (is_mma){
      if (more) load_fp(jt+1, 1-buf);
      // MMA(jt): acc[64x512] += w[64x64] @ fp[64x512]
      const __nv_bfloat16* fcur = fps + (size_t)buf*TJ*FPS;
      const __nv_bfloat16* wcur = ws  + (size_t)buf*64*WSS;
      #pragma unroll
      for (int ks=0;ks<4;ks++){
        uint32_t a[2][4];
        #pragma unroll
        for (int mf=0;mf<2;mf++)
          ldsm4(a[mf], wcur + (size_t)(iw + mf*16 + (lane&15))*WSS + ks*16 + ((lane>>4)<<3));
        #pragma unroll
        for (int nfp=0;nfp<4;nfp++){
          uint32_t t[4];
          int kl = ks*16 + (lane&7) + (((lane>>3)&1)<<3);
          int cl = hw + nfp*16 + (((lane>>4)&1)<<3);
          ldsm4t(t, fcur + (size_t)kl*FPS + cl);
          #pragma unroll
          for (int mf=0;mf<2;mf++){
            mma16816(c[mf][nfp*2+0], a[mf], t);
            mma16816(c[mf][nfp*2+1], a[mf], t+2);
          }
        }
      }
      if (more) cp_wait<0>();      // own fp(jt+1) chunks complete
    } else {
      if (more){
        load_adj(jt+1);
        cp_wait<0>();              // own adj chunks complete (hidden under consumers' MMA)
        wcompute(jt+1, 1-buf);     // writes ws[1-buf]; consumers read ws[buf]
      } else {
        zs[pt] = zp;               // final Z (single owner per row)
      }
    }
    __syncthreads();               // ws(jt+1)+fp(jt+1) visible; all MMA(jt) reads done
  }

  // ---- epilogue: /Z + residual (MMA warps only) ----
  if (is_mma){
    #pragma unroll
    for (int mf=0;mf<2;mf++){
      #pragma unroll
      for (int rr=0;rr<2;rr++){
        int rl = iw + mf*16 + (lane>>2) + rr*8;
        float zinv = 1.0f / zs[rl];
        size_t gro = (size_t)(base + i0 + rl)*HH;
        #pragma unroll
        for (int nf=0;nf<8;nf++){
          int col = hw + nf*8 + ((lane&3)<<1);
          float2 o;
          o.x = c[mf][nf][rr*2+0]*zinv + feats[gro + col + 0];
          o.y = c[mf][nf][rr*2+1]*zinv + feats[gro + col + 1];
          *reinterpret_cast<float2*>(out + gro + col) = o;
        }
      }
    }
  }
}

// ---------------- launch ----------------
extern "C" void kernel_launch(void* const* d_in, const int* in_sizes, int n_in,
                              void* d_out, int out_size){
  const float* feats = (const float*)d_in[0];
  const float* adj   = (const float*)d_in[1];
  const float* fc_w  = (const float*)d_in[2];
  const float* fc_b  = (const float*)d_in[3];
  const float* q_w   = (const float*)d_in[4];
  const float* q_b   = (const float*)d_in[5];
  const float* k_w   = (const float*)d_in[6];
  const float* k_b   = (const float*)d_in[7];
  float* out = (float*)d_out;

  cudaFuncSetAttribute(attn_kernel, cudaFuncAttributeMaxDynamicSharedMemorySize, SMEM_K3);

  // Launch sequence: cvt_all(1), fc_gemm(2), qk_fin(3), attn(4)
  cvt_all_kernel<<<(N4F + 255)/256, 256>>>(feats, fc_w);
  {
    dim3 grid(HH/128, M_TOT/128);
    fc_gemm_kernel<<<grid, 256>>>(fc_b, q_w, k_w);
  }
  qk_fin_kernel<<<(M_TOT+255)/256, 256>>>(q_b, k_b);
  {
    dim3 grid(NN/64, BSZ);
    attn_kernel<<<grid, NTHR, SMEM_K3>>>(adj, feats, out);
  }
}

// round 15
// speedup vs baseline: 1.4540x; 1.4540x over previous
#include <cuda_runtime.h>
#include <cuda_bf16.h>
#include <stdint.h>

#define BSZ 8
#define NN 2048
#define HH 512
#define M_TOT (BSZ*NN)

// ---------------- scratch (device globals; allocation-free) ----------------
__device__ __nv_bfloat16 g_featsb[BSZ*NN*HH];   // feats in bf16
__device__ __nv_bfloat16 g_wb[HH*HH];           // fc_w in bf16  [o][h]
__device__ __nv_bfloat16 g_fpb[BSZ*NN*HH];      // feat_proj in bf16
__device__ float g_qacc[M_TOT], g_kacc[M_TOT];  // atomic partial dots
__device__ __align__(16) float g_qv[M_TOT];
__device__ __align__(16) float g_Eq[M_TOT];
__device__ __align__(16) float g_eq[M_TOT];
__device__ __align__(16) float g_kv[M_TOT];
__device__ __align__(16) float g_Ek[M_TOT];
__device__ __align__(16) float g_ek[M_TOT];

// ---------------- PTX helpers ----------------
__device__ __forceinline__ uint32_t smem_u32(const void* p){
  return (uint32_t)__cvta_generic_to_shared(p);
}
__device__ __forceinline__ void cp_async16(void* s, const void* g){
  asm volatile("cp.async.cg.shared.global [%0], [%1], 16;\n" :: "r"(smem_u32(s)), "l"(g));
}
__device__ __forceinline__ void cp_commit(){ asm volatile("cp.async.commit_group;\n"); }
template<int NG> __device__ __forceinline__ void cp_wait(){
  asm volatile("cp.async.wait_group %0;\n" :: "n"(NG));
}
__device__ __forceinline__ void ldsm4(uint32_t* r, const void* p){
  asm volatile("ldmatrix.sync.aligned.m8n8.x4.shared.b16 {%0,%1,%2,%3}, [%4];\n"
    : "=r"(r[0]),"=r"(r[1]),"=r"(r[2]),"=r"(r[3]) : "r"(smem_u32(p)));
}
__device__ __forceinline__ void ldsm4t(uint32_t* r, const void* p){
  asm volatile("ldmatrix.sync.aligned.m8n8.x4.trans.shared.b16 {%0,%1,%2,%3}, [%4];\n"
    : "=r"(r[0]),"=r"(r[1]),"=r"(r[2]),"=r"(r[3]) : "r"(smem_u32(p)));
}
__device__ __forceinline__ void mma16816(float* c, const uint32_t* a, const uint32_t* b){
  asm volatile("mma.sync.aligned.m16n8k16.row.col.f32.bf16.bf16.f32 "
    "{%0,%1,%2,%3}, {%4,%5,%6,%7}, {%8,%9}, {%0,%1,%2,%3};\n"
    : "+f"(c[0]),"+f"(c[1]),"+f"(c[2]),"+f"(c[3])
    : "r"(a[0]),"r"(a[1]),"r"(a[2]),"r"(a[3]), "r"(b[0]),"r"(b[1]));
}

// ---------------- K0: merged converts (feats->bf16, fc_w->bf16, zero q/k acc) ----------------
#define N4F (BSZ*NN*HH/4)
#define N4W (HH*HH/4)
__global__ void cvt_all_kernel(const float* __restrict__ feats, const float* __restrict__ fc_w){
  int i = blockIdx.x*blockDim.x + threadIdx.x;
  if (i < N4F){
    float4 v = reinterpret_cast<const float4*>(feats)[i];
    reinterpret_cast<__nv_bfloat162*>(g_featsb)[i*2+0] = __floats2bfloat162_rn(v.x, v.y);
    reinterpret_cast<__nv_bfloat162*>(g_featsb)[i*2+1] = __floats2bfloat162_rn(v.z, v.w);
  }
  if (i < N4W){
    float4 v = reinterpret_cast<const float4*>(fc_w)[i];
    reinterpret_cast<__nv_bfloat162*>(g_wb)[i*2+0] = __floats2bfloat162_rn(v.x, v.y);
    reinterpret_cast<__nv_bfloat162*>(g_wb)[i*2+1] = __floats2bfloat162_rn(v.z, v.w);
  }
  if (i < M_TOT){ g_qacc[i] = 0.f; g_kacc[i] = 0.f; }
}

// ---------------- K1: feat_proj GEMM + fused q/k partial dots ----------------
__global__ __launch_bounds__(256) void fc_gemm_kernel(const float* __restrict__ fc_b,
                                                      const float* __restrict__ qw_,
                                                      const float* __restrict__ kw_){
  __shared__ __nv_bfloat16 As[2][128][40];
  __shared__ __nv_bfloat16 Bs[2][128][40];
  const int tid = threadIdx.x, lane = tid & 31, warp = tid >> 5;
  const int m0 = blockIdx.y*128, n0 = blockIdx.x*128;
  const int wm = warp >> 1, wn = warp & 1;
  const int m_off = wm*32, n_off = wn*64;

  float c[2][8][4];
  #pragma unroll
  for (int a=0;a<2;a++) for (int b=0;b<8;b++) for (int d=0;d<4;d++) c[a][b][d]=0.f;

  auto load_chunk = [&](int kc, int buf){
    int k0 = kc*32;
    #pragma unroll
    for (int s2=0;s2<2;s2++){
      int s = tid + s2*256;
      int row = s >> 2, c8 = (s & 3) << 3;
      cp_async16(&As[buf][row][c8], g_featsb + (size_t)(m0+row)*HH + k0 + c8);
      cp_async16(&Bs[buf][row][c8], g_wb     + (size_t)(n0+row)*HH + k0 + c8);
    }
    cp_commit();
  };

  load_chunk(0,0);
  for (int kc=0;kc<16;kc++){
    if (kc+1<16) { load_chunk(kc+1,(kc+1)&1); cp_wait<1>(); }
    else         { cp_wait<0>(); }
    __syncthreads();
    const int cur = kc & 1;
    #pragma unroll
    for (int ks=0;ks<2;ks++){
      uint32_t a[2][4];
      #pragma unroll
      for (int mf=0;mf<2;mf++)
        ldsm4(a[mf], &As[cur][m_off + mf*16 + (lane&15)][ks*16 + ((lane>>4)<<3)]);
      uint32_t bb[8][2];
      #pragma unroll
      for (int nf2=0;nf2<4;nf2++){
        uint32_t t[4];
        int nl = n_off + nf2*16 + (lane&7) + (((lane>>4)&1)<<3);
        int kl = ks*16 + (((lane>>3)&1)<<3);
        ldsm4(t, &Bs[cur][nl][kl]);
        bb[nf2*2+0][0]=t[0]; bb[nf2*2+0][1]=t[1];
        bb[nf2*2+1][0]=t[2]; bb[nf2*2+1][1]=t[3];
      }
      #pragma unroll
      for (int mf=0;mf<2;mf++)
        #pragma unroll
        for (int nf=0;nf<8;nf++)
          mma16816(c[mf][nf], a[mf], bb[nf]);
    }
    __syncthreads();
  }
  // epilogue: +bias, store bf16, accumulate q/k partial dots
  float qp[2][2] = {{0.f,0.f},{0.f,0.f}};
  float kp[2][2] = {{0.f,0.f},{0.f,0.f}};
  #pragma unroll
  for (int mf=0;mf<2;mf++){
    #pragma unroll
    for (int nf=0;nf<8;nf++){
      int col = n0 + n_off + nf*8 + ((lane&3)<<1);
      float b0 = __ldg(&fc_b[col]), b1 = __ldg(&fc_b[col+1]);
      float qw0 = __ldg(&qw_[col]), qw1 = __ldg(&qw_[col+1]);
      float kw0 = __ldg(&kw_[col]), kw1 = __ldg(&kw_[col+1]);
      #pragma unroll
      for (int rr=0;rr<2;rr++){
        int row = m0 + m_off + mf*16 + (lane>>2) + rr*8;
        float v0 = c[mf][nf][rr*2+0] + b0;
        float v1 = c[mf][nf][rr*2+1] + b1;
        *reinterpret_cast<__nv_bfloat162*>(&g_fpb[(size_t)row*HH + col]) =
            __floats2bfloat162_rn(v0, v1);
        qp[mf][rr] += v0*qw0 + v1*qw1;
        kp[mf][rr] += v0*kw0 + v1*kw1;
      }
    }
  }
  #pragma unroll
  for (int mf=0;mf<2;mf++){
    #pragma unroll
    for (int rr=0;rr<2;rr++){
      float q = qp[mf][rr], k = kp[mf][rr];
      q += __shfl_xor_sync(0xffffffffu, q, 1);
      q += __shfl_xor_sync(0xffffffffu, q, 2);
      k += __shfl_xor_sync(0xffffffffu, k, 1);
      k += __shfl_xor_sync(0xffffffffu, k, 2);
      if ((lane & 3) == 0){
        int row = m0 + m_off + mf*16 + (lane>>2) + rr*8;
        atomicAdd(&g_qacc[row], q);
        atomicAdd(&g_kacc[row], k);
      }
    }
  }
}

// ---------------- K2: finalize q/k + exp precompute ----------------
__global__ void qk_fin_kernel(const float* __restrict__ qb, const float* __restrict__ kb){
  int i = blockIdx.x*blockDim.x + threadIdx.x;
  if (i < M_TOT){
    float q = g_qacc[i] + __ldg(qb);
    float k = g_kacc[i] + __ldg(kb);
    g_qv[i]=q; g_Eq[i]=expf(q); g_eq[i]=expf(0.01f*q);
    g_kv[i]=k; g_Ek[i]=expf(k); g_ek[i]=expf(0.01f*k);
  }
}

// ---------------- K3: masked-softmax attention + residual ----------------
// R8 attn + (1) adj in register prefetch (no adj smem, no cp_wait<1>),
//          + (2) k-params staged in smem (LDS instead of __ldg chains).
#define TJ 64
#define NT (NN/TJ)
#define FPS 520   // fp tile stride (bf16)
#define WSS 72    // w tile stride (bf16): 64 + 8 pad
#define SMEM_K3 (2*TJ*FPS*2 + 2*64*WSS*2 + 3*NN*4 + 4*64*4)

__global__ __launch_bounds__(512,1) void attn_kernel(const float* __restrict__ adj,
                                                     const float* __restrict__ feats,
                                                     float* __restrict__ out){
  extern __shared__ char smraw[];
  __nv_bfloat16* fps = (__nv_bfloat16*)smraw;                          // [2][64][520]
  __nv_bfloat16* ws  = (__nv_bfloat16*)(smraw + 2*TJ*FPS*2);           // [2][64][72]
  float* sk   = (float*)(smraw + 2*TJ*FPS*2 + 2*64*WSS*2);             // [2048]
  float* sE   = sk + NN;
  float* se   = sE + NN;
  float* rq   = se + NN;     // [64]
  float* rEq  = rq + 64;
  float* req  = rEq + 64;
  float* zs   = req + 64;    // [64]

  const int tid = threadIdx.x, lane = tid & 31, warp = tid >> 5;
  const int b  = blockIdx.y;
  const int i0 = blockIdx.x*64;
  const int base = b*NN;

  if (tid < 64){ rq[tid]=g_qv[base+i0+tid]; rEq[tid]=g_Eq[base+i0+tid]; req[tid]=g_eq[base+i0+tid]; }

  const int ii = tid >> 3;           // w-compute / adj row (0..63)
  const int j4 = (tid & 7) << 2;     // w-compute / adj col base
  const float* adjrow = adj + (size_t)(base + i0 + ii)*NN + j4;

  auto load_fp = [&](int jt, int buf){
    const __nv_bfloat16* src = g_fpb + (size_t)(base + jt*TJ)*HH;
    #pragma unroll
    for (int s=0;s<8;s++){
      int seg = tid + s*512;
      int row = seg >> 6, hs = (seg & 63) << 3;
      cp_async16(&fps[(size_t)buf*TJ*FPS + row*FPS + hs], src + (size_t)row*HH + hs);
    }
    cp_commit();
  };

  // adj prefetch registers: this thread's 8 cols of the (jt) tile
  float4 apf[2];
  auto adj_prefetch = [&](int jt){
    const float* p = adjrow + jt*TJ;
    apf[0] = __ldg(reinterpret_cast<const float4*>(p));
    apf[1] = __ldg(reinterpret_cast<const float4*>(p + 32));
  };

  float c[2][8][4];
  #pragma unroll
  for (int a=0;a<2;a++) for (int nb=0;nb<8;nb++) for (int d=0;d<4;d++) c[a][nb][d]=0.f;
  float zp = 0.f;
  const int wm = warp >> 3, wn = warp & 7;
  const int iw = wm*32, hw = wn*64;

  auto wcompute = [&](int jt, int buf){
    float qi = rq[ii], Eqi = rEq[ii], eqi = req[ii];
    #pragma unroll
    for (int half=0; half<2; half++){
      int jj = j4 + half*32;
      int j  = jt*TJ + jj;
      float4 a4 = apf[half];
      float4 k4 = *reinterpret_cast<const float4*>(&sk[j]);
      float4 E4 = *reinterpret_cast<const float4*>(&sE[j]);
      float4 e4 = *reinterpret_cast<const float4*>(&se[j]);
      float w0 = a4.x * ((qi + k4.x >= 0.f) ? Eqi*E4.x : eqi*e4.x);
      float w1 = a4.y * ((qi + k4.y >= 0.f) ? Eqi*E4.y : eqi*e4.y);
      float w2 = a4.z * ((qi + k4.z >= 0.f) ? Eqi*E4.z : eqi*e4.z);
      float w3 = a4.w * ((qi + k4.w >= 0.f) ? Eqi*E4.w : eqi*e4.w);
      zp += (w0 + w1) + (w2 + w3);
      __nv_bfloat16* wrow = &ws[(size_t)buf*64*WSS + ii*WSS + jj];
      *reinterpret_cast<__nv_bfloat162*>(wrow + 0) = __floats2bfloat162_rn(w0, w1);
      *reinterpret_cast<__nv_bfloat162*>(wrow + 2) = __floats2bfloat162_rn(w2, w3);
    }
  };

  // ---- prologue: stage k-params + fp(0); adj(0) in regs ----
  {
    // 3 arrays x 2048 f32 = 1536 x 16B chunks; 3 chunks per thread
    int seg = tid;  // 0..511
    cp_async16(&sk[seg*4], g_kv + base + seg*4);
    cp_async16(&sE[seg*4], g_Ek + base + seg*4);
    cp_async16(&se[seg*4], g_ek + base + seg*4);
    cp_commit();
  }
  load_fp(0,0);
  adj_prefetch(0);
  cp_wait<0>();
  __syncthreads();               // params + fp(0) visible
  wcompute(0,0);                 // uses apf(0), writes ws[0]
  adj_prefetch(1);
  __syncthreads();               // ws(0) visible

  // ---- main loop: one barrier per iteration ----
  for (int jt=0; jt<NT; jt++){
    const int buf = jt & 1;
    const bool more = (jt+1 < NT);
    if (more) load_fp(jt+1, 1-buf);

    // MMA(jt): acc[64x512] += w[64x64] @ fp[64x512]
    const __nv_bfloat16* fcur = fps + (size_t)buf*TJ*FPS;
    const __nv_bfloat16* wcur = ws  + (size_t)buf*64*WSS;
    #pragma unroll
    for (int ks=0;ks<4;ks++){
      uint32_t a[2][4];
      #pragma unroll
      for (int mf=0;mf<2;mf++)
        ldsm4(a[mf], wcur + (size_t)(iw + mf*16 + (lane&15))*WSS + ks*16 + ((lane>>4)<<3));
      #pragma unroll
      for (int nfp=0;nfp<4;nfp++){
        uint32_t t[4];
        int kl = ks*16 + (lane&7) + (((lane>>3)&1)<<3);
        int cl = hw + nfp*16 + (((lane>>4)&1)<<3);
        ldsm4t(t, fcur + (size_t)kl*FPS + cl);
        #pragma unroll
        for (int mf=0;mf<2;mf++){
          mma16816(c[mf][nfp*2+0], a[mf], t);
          mma16816(c[mf][nfp*2+1], a[mf], t+2);
        }
      }
    }

    if (more){
      wcompute(jt+1, 1-buf);     // apf holds adj(jt+1); writes ws[1-buf]
      if (jt+2 < NT) adj_prefetch(jt+2);
      cp_wait<0>();              // fp(jt+1) complete for this thread
    }
    __syncthreads();             // ws(jt+1)+fp(jt+1) visible; all warps done MMA(jt)
  }

  // ---- Z reduction: 8 threads per row ----
  {
    float z = zp;
    z += __shfl_down_sync(0xffffffffu, z, 4, 8);
    z += __shfl_down_sync(0xffffffffu, z, 2, 8);
    z += __shfl_down_sync(0xffffffffu, z, 1, 8);
    if ((lane & 7) == 0) zs[ii] = z;
  }
  __syncthreads();

  // ---- epilogue: /Z + residual ----
  #pragma unroll
  for (int mf=0;mf<2;mf++){
    #pragma unroll
    for (int rr=0;rr<2;rr++){
      int rl = iw + mf*16 + (lane>>2) + rr*8;
      float zinv = 1.0f / zs[rl];
      size_t gro = (size_t)(base + i0 + rl)*HH;
      #pragma unroll
      for (int nf=0;nf<8;nf++){
        int col = hw + nf*8 + ((lane&3)<<1);
        float2 o;
        o.x = c[mf][nf][rr*2+0]*zinv + feats[gro + col + 0];
        o.y = c[mf][nf][rr*2+1]*zinv + feats[gro + col + 1];
        *reinterpret_cast<float2*>(out + gro + col) = o;
      }
    }
  }
}

// ---------------- launch ----------------
extern "C" void kernel_launch(void* const* d_in, const int* in_sizes, int n_in,
                              void* d_out, int out_size){
  const float* feats = (const float*)d_in[0];
  const float* adj   = (const float*)d_in[1];
  const float* fc_w  = (const float*)d_in[2];
  const float* fc_b  = (const float*)d_in[3];
  const float* q_w   = (const float*)d_in[4];
  const float* q_b   = (const float*)d_in[5];
  const float* k_w   = (const float*)d_in[6];
  const float* k_b   = (const float*)d_in[7];
  float* out = (float*)d_out;

  cudaFuncSetAttribute(attn_kernel, cudaFuncAttributeMaxDynamicSharedMemorySize, SMEM_K3);

  // Launch sequence: cvt_all(1), fc_gemm(2), qk_fin(3), attn(4)
  cvt_all_kernel<<<(N4F + 255)/256, 256>>>(feats, fc_w);
  {
    dim3 grid(HH/128, M_TOT/128);
    fc_gemm_kernel<<<grid, 256>>>(fc_b, q_w, k_w);
  }
  qk_fin_kernel<<<(M_TOT+255)/256, 256>>>(q_b, k_b);
  {
    dim3 grid(NN/64, BSZ);
    attn_kernel<<<grid, 512, SMEM_K3>>>(adj, feats, out);
  }
}

// round 16
// speedup vs baseline: 1.4551x; 1.0008x over previous
#include <cuda_runtime.h>
#include <cuda_bf16.h>
#include <stdint.h>

#define BSZ 8
#define NN 2048
#define HH 512
#define M_TOT (BSZ*NN)

// ---------------- scratch (device globals; allocation-free) ----------------
__device__ __nv_bfloat16 g_featsb[BSZ*NN*HH];   // feats in bf16
__device__ __nv_bfloat16 g_wb[HH*HH];           // fc_w in bf16  [o][h]
__device__ __nv_bfloat16 g_fpb[BSZ*NN*HH];      // feat_proj in bf16
__device__ float g_qacc[M_TOT], g_kacc[M_TOT];  // atomic partial dots
__device__ __align__(16) float g_qv[M_TOT];
__device__ __align__(16) float g_Eq[M_TOT];
__device__ __align__(16) float g_eq[M_TOT];
__device__ __align__(16) float g_kv[M_TOT];
__device__ __align__(16) float g_Ek[M_TOT];
__device__ __align__(16) float g_ek[M_TOT];

// ---------------- PTX helpers ----------------
__device__ __forceinline__ uint32_t smem_u32(const void* p){
  return (uint32_t)__cvta_generic_to_shared(p);
}
__device__ __forceinline__ void cp_async16(void* s, const void* g){
  asm volatile("cp.async.cg.shared.global [%0], [%1], 16;\n" :: "r"(smem_u32(s)), "l"(g));
}
__device__ __forceinline__ void cp_commit(){ asm volatile("cp.async.commit_group;\n"); }
template<int NG> __device__ __forceinline__ void cp_wait(){
  asm volatile("cp.async.wait_group %0;\n" :: "n"(NG));
}
__device__ __forceinline__ void ldsm4(uint32_t* r, const void* p){
  asm volatile("ldmatrix.sync.aligned.m8n8.x4.shared.b16 {%0,%1,%2,%3}, [%4];\n"
    : "=r"(r[0]),"=r"(r[1]),"=r"(r[2]),"=r"(r[3]) : "r"(smem_u32(p)));
}
__device__ __forceinline__ void ldsm4t(uint32_t* r, const void* p){
  asm volatile("ldmatrix.sync.aligned.m8n8.x4.trans.shared.b16 {%0,%1,%2,%3}, [%4];\n"
    : "=r"(r[0]),"=r"(r[1]),"=r"(r[2]),"=r"(r[3]) : "r"(smem_u32(p)));
}
__device__ __forceinline__ void mma16816(float* c, const uint32_t* a, const uint32_t* b){
  asm volatile("mma.sync.aligned.m16n8k16.row.col.f32.bf16.bf16.f32 "
    "{%0,%1,%2,%3}, {%4,%5,%6,%7}, {%8,%9}, {%0,%1,%2,%3};\n"
    : "+f"(c[0]),"+f"(c[1]),"+f"(c[2]),"+f"(c[3])
    : "r"(a[0]),"r"(a[1]),"r"(a[2]),"r"(a[3]), "r"(b[0]),"r"(b[1]));
}

// ---------------- K0: merged converts (feats->bf16, fc_w->bf16, zero q/k acc) ----------------
#define N4F (BSZ*NN*HH/4)
#define N4W (HH*HH/4)
__global__ void cvt_all_kernel(const float* __restrict__ feats, const float* __restrict__ fc_w){
  int i = blockIdx.x*blockDim.x + threadIdx.x;
  if (i < N4F){
    float4 v = reinterpret_cast<const float4*>(feats)[i];
    reinterpret_cast<__nv_bfloat162*>(g_featsb)[i*2+0] = __floats2bfloat162_rn(v.x, v.y);
    reinterpret_cast<__nv_bfloat162*>(g_featsb)[i*2+1] = __floats2bfloat162_rn(v.z, v.w);
  }
  if (i < N4W){
    float4 v = reinterpret_cast<const float4*>(fc_w)[i];
    reinterpret_cast<__nv_bfloat162*>(g_wb)[i*2+0] = __floats2bfloat162_rn(v.x, v.y);
    reinterpret_cast<__nv_bfloat162*>(g_wb)[i*2+1] = __floats2bfloat162_rn(v.z, v.w);
  }
  if (i < M_TOT){ g_qacc[i] = 0.f; g_kacc[i] = 0.f; }
}

// ---------------- K1: feat_proj GEMM + fused q/k partial dots ----------------
__global__ __launch_bounds__(256) void fc_gemm_kernel(const float* __restrict__ fc_b,
                                                      const float* __restrict__ qw_,
                                                      const float* __restrict__ kw_){
  __shared__ __nv_bfloat16 As[2][128][40];
  __shared__ __nv_bfloat16 Bs[2][128][40];
  const int tid = threadIdx.x, lane = tid & 31, warp = tid >> 5;
  const int m0 = blockIdx.y*128, n0 = blockIdx.x*128;
  const int wm = warp >> 1, wn = warp & 1;
  const int m_off = wm*32, n_off = wn*64;

  float c[2][8][4];
  #pragma unroll
  for (int a=0;a<2;a++) for (int b=0;b<8;b++) for (int d=0;d<4;d++) c[a][b][d]=0.f;

  auto load_chunk = [&](int kc, int buf){
    int k0 = kc*32;
    #pragma unroll
    for (int s2=0;s2<2;s2++){
      int s = tid + s2*256;
      int row = s >> 2, c8 = (s & 3) << 3;
      cp_async16(&As[buf][row][c8], g_featsb + (size_t)(m0+row)*HH + k0 + c8);
      cp_async16(&Bs[buf][row][c8], g_wb     + (size_t)(n0+row)*HH + k0 + c8);
    }
    cp_commit();
  };

  load_chunk(0,0);
  for (int kc=0;kc<16;kc++){
    if (kc+1<16) { load_chunk(kc+1,(kc+1)&1); cp_wait<1>(); }
    else         { cp_wait<0>(); }
    __syncthreads();
    const int cur = kc & 1;
    #pragma unroll
    for (int ks=0;ks<2;ks++){
      uint32_t a[2][4];
      #pragma unroll
      for (int mf=0;mf<2;mf++)
        ldsm4(a[mf], &As[cur][m_off + mf*16 + (lane&15)][ks*16 + ((lane>>4)<<3)]);
      uint32_t bb[8][2];
      #pragma unroll
      for (int nf2=0;nf2<4;nf2++){
        uint32_t t[4];
        int nl = n_off + nf2*16 + (lane&7) + (((lane>>4)&1)<<3);
        int kl = ks*16 + (((lane>>3)&1)<<3);
        ldsm4(t, &Bs[cur][nl][kl]);
        bb[nf2*2+0][0]=t[0]; bb[nf2*2+0][1]=t[1];
        bb[nf2*2+1][0]=t[2]; bb[nf2*2+1][1]=t[3];
      }
      #pragma unroll
      for (int mf=0;mf<2;mf++)
        #pragma unroll
        for (int nf=0;nf<8;nf++)
          mma16816(c[mf][nf], a[mf], bb[nf]);
    }
    __syncthreads();
  }
  // epilogue: +bias, store bf16, accumulate q/k partial dots
  float qp[2][2] = {{0.f,0.f},{0.f,0.f}};
  float kp[2][2] = {{0.f,0.f},{0.f,0.f}};
  #pragma unroll
  for (int mf=0;mf<2;mf++){
    #pragma unroll
    for (int nf=0;nf<8;nf++){
      int col = n0 + n_off + nf*8 + ((lane&3)<<1);
      float b0 = __ldg(&fc_b[col]), b1 = __ldg(&fc_b[col+1]);
      float qw0 = __ldg(&qw_[col]), qw1 = __ldg(&qw_[col+1]);
      float kw0 = __ldg(&kw_[col]), kw1 = __ldg(&kw_[col+1]);
      #pragma unroll
      for (int rr=0;rr<2;rr++){
        int row = m0 + m_off + mf*16 + (lane>>2) + rr*8;
        float v0 = c[mf][nf][rr*2+0] + b0;
        float v1 = c[mf][nf][rr*2+1] + b1;
        *reinterpret_cast<__nv_bfloat162*>(&g_fpb[(size_t)row*HH + col]) =
            __floats2bfloat162_rn(v0, v1);
        qp[mf][rr] += v0*qw0 + v1*qw1;
        kp[mf][rr] += v0*kw0 + v1*kw1;
      }
    }
  }
  #pragma unroll
  for (int mf=0;mf<2;mf++){
    #pragma unroll
    for (int rr=0;rr<2;rr++){
      float q = qp[mf][rr], k = kp[mf][rr];
      q += __shfl_xor_sync(0xffffffffu, q, 1);
      q += __shfl_xor_sync(0xffffffffu, q, 2);
      k += __shfl_xor_sync(0xffffffffu, k, 1);
      k += __shfl_xor_sync(0xffffffffu, k, 2);
      if ((lane & 3) == 0){
        int row = m0 + m_off + mf*16 + (lane>>2) + rr*8;
        atomicAdd(&g_qacc[row], q);
        atomicAdd(&g_kacc[row], k);
      }
    }
  }
}

// ---------------- K2: finalize q/k + exp precompute ----------------
__global__ void qk_fin_kernel(const float* __restrict__ qb, const float* __restrict__ kb){
  int i = blockIdx.x*blockDim.x + threadIdx.x;
  if (i < M_TOT){
    float q = g_qacc[i] + __ldg(qb);
    float k = g_kacc[i] + __ldg(kb);
    g_qv[i]=q; g_Eq[i]=expf(q); g_eq[i]=expf(0.01f*q);
    g_kv[i]=k; g_Ek[i]=expf(k); g_ek[i]=expf(0.01f*k);
  }
}

// ---------------- K3: masked-softmax attention + residual ----------------
// R15 + (1) B-fragment software pipeline in the MMA loop,
//       (2) qi/Eqi/eqi hoisted to loop-invariant registers.
#define TJ 64
#define NT (NN/TJ)
#define FPS 520   // fp tile stride (bf16)
#define WSS 72    // w tile stride (bf16): 64 + 8 pad
#define SMEM_K3 (2*TJ*FPS*2 + 2*64*WSS*2 + 3*NN*4 + 4*64*4)

__global__ __launch_bounds__(512,1) void attn_kernel(const float* __restrict__ adj,
                                                     const float* __restrict__ feats,
                                                     float* __restrict__ out){
  extern __shared__ char smraw[];
  __nv_bfloat16* fps = (__nv_bfloat16*)smraw;                          // [2][64][520]
  __nv_bfloat16* ws  = (__nv_bfloat16*)(smraw + 2*TJ*FPS*2);           // [2][64][72]
  float* sk   = (float*)(smraw + 2*TJ*FPS*2 + 2*64*WSS*2);             // [2048]
  float* sE   = sk + NN;
  float* se   = sE + NN;
  float* rq   = se + NN;     // [64]
  float* rEq  = rq + 64;
  float* req  = rEq + 64;
  float* zs   = req + 64;    // [64]

  const int tid = threadIdx.x, lane = tid & 31, warp = tid >> 5;
  const int b  = blockIdx.y;
  const int i0 = blockIdx.x*64;
  const int base = b*NN;

  if (tid < 64){ rq[tid]=g_qv[base+i0+tid]; rEq[tid]=g_Eq[base+i0+tid]; req[tid]=g_eq[base+i0+tid]; }

  const int ii = tid >> 3;           // w-compute / adj row (0..63)
  const int j4 = (tid & 7) << 2;     // w-compute / adj col base
  const float* adjrow = adj + (size_t)(base + i0 + ii)*NN + j4;

  auto load_fp = [&](int jt, int buf){
    const __nv_bfloat16* src = g_fpb + (size_t)(base + jt*TJ)*HH;
    #pragma unroll
    for (int s=0;s<8;s++){
      int seg = tid + s*512;
      int row = seg >> 6, hs = (seg & 63) << 3;
      cp_async16(&fps[(size_t)buf*TJ*FPS + row*FPS + hs], src + (size_t)row*HH + hs);
    }
    cp_commit();
  };

  // adj prefetch registers: this thread's 8 cols of the (jt) tile
  float4 apf[2];
  auto adj_prefetch = [&](int jt){
    const float* p = adjrow + jt*TJ;
    apf[0] = __ldg(reinterpret_cast<const float4*>(p));
    apf[1] = __ldg(reinterpret_cast<const float4*>(p + 32));
  };

  float c[2][8][4];
  #pragma unroll
  for (int a=0;a<2;a++) for (int nb=0;nb<8;nb++) for (int d=0;d<4;d++) c[a][nb][d]=0.f;
  float zp = 0.f;
  const int wm = warp >> 3, wn = warp & 7;
  const int iw = wm*32, hw = wn*64;

  // ---- prologue: stage k-params + fp(0); adj(0) in regs ----
  {
    int seg = tid;  // 0..511
    cp_async16(&sk[seg*4], g_kv + base + seg*4);
    cp_async16(&sE[seg*4], g_Ek + base + seg*4);
    cp_async16(&se[seg*4], g_ek + base + seg*4);
    cp_commit();
  }
  load_fp(0,0);
  adj_prefetch(0);
  cp_wait<0>();
  __syncthreads();               // params + fp(0) visible

  // loop-invariant row params (hoisted out of wcompute)
  const float qi = rq[ii], Eqi = rEq[ii], eqi = req[ii];

  auto wcompute = [&](int jt, int buf){
    #pragma unroll
    for (int half=0; half<2; half++){
      int jj = j4 + half*32;
      int j  = jt*TJ + jj;
      float4 a4 = apf[half];
      float4 k4 = *reinterpret_cast<const float4*>(&sk[j]);
      float4 E4 = *reinterpret_cast<const float4*>(&sE[j]);
      float4 e4 = *reinterpret_cast<const float4*>(&se[j]);
      float w0 = a4.x * ((qi + k4.x >= 0.f) ? Eqi*E4.x : eqi*e4.x);
      float w1 = a4.y * ((qi + k4.y >= 0.f) ? Eqi*E4.y : eqi*e4.y);
      float w2 = a4.z * ((qi + k4.z >= 0.f) ? Eqi*E4.z : eqi*e4.z);
      float w3 = a4.w * ((qi + k4.w >= 0.f) ? Eqi*E4.w : eqi*e4.w);
      zp += (w0 + w1) + (w2 + w3);
      __nv_bfloat16* wrow = &ws[(size_t)buf*64*WSS + ii*WSS + jj];
      *reinterpret_cast<__nv_bfloat162*>(wrow + 0) = __floats2bfloat162_rn(w0, w1);
      *reinterpret_cast<__nv_bfloat162*>(wrow + 2) = __floats2bfloat162_rn(w2, w3);
    }
  };

  wcompute(0,0);                 // uses apf(0), writes ws[0]
  adj_prefetch(1);
  __syncthreads();               // ws(0) visible

  // ---- main loop: one barrier per iteration ----
  for (int jt=0; jt<NT; jt++){
    const int buf = jt & 1;
    const bool more = (jt+1 < NT);
    if (more) load_fp(jt+1, 1-buf);

    // MMA(jt): acc[64x512] += w[64x64] @ fp[64x512]; B-frags software-pipelined
    const __nv_bfloat16* fcur = fps + (size_t)buf*TJ*FPS;
    const __nv_bfloat16* wcur = ws  + (size_t)buf*64*WSS;
    const int klq = (lane&7) + (((lane>>3)&1)<<3);        // k-lane within 16
    const int clq = hw + (((lane>>4)&1)<<3);              // col-lane base
    #pragma unroll
    for (int ks=0;ks<4;ks++){
      uint32_t a[2][4];
      #pragma unroll
      for (int mf=0;mf<2;mf++)
        ldsm4(a[mf], wcur + (size_t)(iw + mf*16 + (lane&15))*WSS + ks*16 + ((lane>>4)<<3));
      uint32_t t0[4], t1[4];
      ldsm4t(t0, fcur + (size_t)(ks*16 + klq)*FPS + clq);          // nfp=0
      #pragma unroll
      for (int nfp=0;nfp<4;nfp++){
        uint32_t* tc = (nfp & 1) ? t1 : t0;
        uint32_t* tn = (nfp & 1) ? t0 : t1;
        if (nfp < 3)
          ldsm4t(tn, fcur + (size_t)(ks*16 + klq)*FPS + clq + (nfp+1)*16);
        #pragma unroll
        for (int mf=0;mf<2;mf++){
          mma16816(c[mf][nfp*2+0], a[mf], tc);
          mma16816(c[mf][nfp*2+1], a[mf], tc+2);
        }
      }
    }

    if (more){
      wcompute(jt+1, 1-buf);     // apf holds adj(jt+1); writes ws[1-buf]
      if (jt+2 < NT) adj_prefetch(jt+2);
      cp_wait<0>();              // fp(jt+1) complete for this thread
    }
    __syncthreads();             // ws(jt+1)+fp(jt+1) visible; all warps done MMA(jt)
  }

  // ---- Z reduction: 8 threads per row ----
  {
    float z = zp;
    z += __shfl_down_sync(0xffffffffu, z, 4, 8);
    z += __shfl_down_sync(0xffffffffu, z, 2, 8);
    z += __shfl_down_sync(0xffffffffu, z, 1, 8);
    if ((lane & 7) == 0) zs[ii] = z;
  }
  __syncthreads();

  // ---- epilogue: /Z + residual ----
  #pragma unroll
  for (int mf=0;mf<2;mf++){
    #pragma unroll
    for (int rr=0;rr<2;rr++){
      int rl = iw + mf*16 + (lane>>2) + rr*8;
      float zinv = 1.0f / zs[rl];
      size_t gro = (size_t)(base + i0 + rl)*HH;
      #pragma unroll
      for (int nf=0;nf<8;nf++){
        int col = hw + nf*8 + ((lane&3)<<1);
        float2 o;
        o.x = c[mf][nf][rr*2+0]*zinv + feats[gro + col + 0];
        o.y = c[mf][nf][rr*2+1]*zinv + feats[gro + col + 1];
        *reinterpret_cast<float2*>(out + gro + col) = o;
      }
    }
  }
}

// ---------------- launch ----------------
extern "C" void kernel_launch(void* const* d_in, const int* in_sizes, int n_in,
                              void* d_out, int out_size){
  const float* feats = (const float*)d_in[0];
  const float* adj   = (const float*)d_in[1];
  const float* fc_w  = (const float*)d_in[2];
  const float* fc_b  = (const float*)d_in[3];
  const float* q_w   = (const float*)d_in[4];
  const float* q_b   = (const float*)d_in[5];
  const float* k_w   = (const float*)d_in[6];
  const float* k_b   = (const float*)d_in[7];
  float* out = (float*)d_out;

  cudaFuncSetAttribute(attn_kernel, cudaFuncAttributeMaxDynamicSharedMemorySize, SMEM_K3);

  // Launch sequence: cvt_all(1), fc_gemm(2), qk_fin(3), attn(4)
  cvt_all_kernel<<<(N4F + 255)/256, 256>>>(feats, fc_w);
  {
    dim3 grid(HH/128, M_TOT/128);
    fc_gemm_kernel<<<grid, 256>>>(fc_b, q_w, k_w);
  }
  qk_fin_kernel<<<(M_TOT+255)/256, 256>>>(q_b, k_b);
  {
    dim3 grid(NN/64, BSZ);
    attn_kernel<<<grid, 512, SMEM_K3>>>(adj, feats, out);
  }
}

// round 17
// speedup vs baseline: 1.4583x; 1.0022x over previous
#include <cuda_runtime.h>
#include <cuda_bf16.h>
#include <stdint.h>

#define BSZ 8
#define NN 2048
#define HH 512
#define M_TOT (BSZ*NN)

// ---------------- scratch (device globals; allocation-free) ----------------
__device__ __nv_bfloat16 g_featsb[BSZ*NN*HH];   // feats in bf16
__device__ __nv_bfloat16 g_wb[HH*HH];           // fc_w in bf16  [o][h]
__device__ __nv_bfloat16 g_fpb[BSZ*NN*HH];      // feat_proj in bf16
__device__ float g_qacc[M_TOT], g_kacc[M_TOT];  // atomic partial dots
__device__ __align__(16) float g_qv[M_TOT];
__device__ __align__(16) float g_Eq[M_TOT];
__device__ __align__(16) float g_eq[M_TOT];
__device__ __align__(16) float g_kv[M_TOT];
__device__ __align__(16) float g_Ek[M_TOT];
__device__ __align__(16) float g_ek[M_TOT];

// ---------------- PTX helpers ----------------
__device__ __forceinline__ uint32_t smem_u32(const void* p){
  return (uint32_t)__cvta_generic_to_shared(p);
}
__device__ __forceinline__ void cp_async16(void* s, const void* g){
  asm volatile("cp.async.cg.shared.global [%0], [%1], 16;\n" :: "r"(smem_u32(s)), "l"(g));
}
__device__ __forceinline__ void cp_commit(){ asm volatile("cp.async.commit_group;\n"); }
template<int NG> __device__ __forceinline__ void cp_wait(){
  asm volatile("cp.async.wait_group %0;\n" :: "n"(NG));
}
__device__ __forceinline__ void ldsm4(uint32_t* r, const void* p){
  asm volatile("ldmatrix.sync.aligned.m8n8.x4.shared.b16 {%0,%1,%2,%3}, [%4];\n"
    : "=r"(r[0]),"=r"(r[1]),"=r"(r[2]),"=r"(r[3]) : "r"(smem_u32(p)));
}
__device__ __forceinline__ void ldsm4t(uint32_t* r, const void* p){
  asm volatile("ldmatrix.sync.aligned.m8n8.x4.trans.shared.b16 {%0,%1,%2,%3}, [%4];\n"
    : "=r"(r[0]),"=r"(r[1]),"=r"(r[2]),"=r"(r[3]) : "r"(smem_u32(p)));
}
__device__ __forceinline__ void mma16816(float* c, const uint32_t* a, const uint32_t* b){
  asm volatile("mma.sync.aligned.m16n8k16.row.col.f32.bf16.bf16.f32 "
    "{%0,%1,%2,%3}, {%4,%5,%6,%7}, {%8,%9}, {%0,%1,%2,%3};\n"
    : "+f"(c[0]),"+f"(c[1]),"+f"(c[2]),"+f"(c[3])
    : "r"(a[0]),"r"(a[1]),"r"(a[2]),"r"(a[3]), "r"(b[0]),"r"(b[1]));
}

// ---------------- K0: merged converts (feats->bf16, fc_w->bf16, zero q/k acc) ----------------
#define N4F (BSZ*NN*HH/4)
#define N4W (HH*HH/4)
__global__ void cvt_all_kernel(const float* __restrict__ feats, const float* __restrict__ fc_w){
  int i = blockIdx.x*blockDim.x + threadIdx.x;
  if (i < N4F){
    float4 v = reinterpret_cast<const float4*>(feats)[i];
    reinterpret_cast<__nv_bfloat162*>(g_featsb)[i*2+0] = __floats2bfloat162_rn(v.x, v.y);
    reinterpret_cast<__nv_bfloat162*>(g_featsb)[i*2+1] = __floats2bfloat162_rn(v.z, v.w);
  }
  if (i < N4W){
    float4 v = reinterpret_cast<const float4*>(fc_w)[i];
    reinterpret_cast<__nv_bfloat162*>(g_wb)[i*2+0] = __floats2bfloat162_rn(v.x, v.y);
    reinterpret_cast<__nv_bfloat162*>(g_wb)[i*2+1] = __floats2bfloat162_rn(v.z, v.w);
  }
  if (i < M_TOT){ g_qacc[i] = 0.f; g_kacc[i] = 0.f; }
}

// ---------------- K1: feat_proj GEMM + fused q/k partial dots ----------------
__global__ __launch_bounds__(256) void fc_gemm_kernel(const float* __restrict__ fc_b,
                                                      const float* __restrict__ qw_,
                                                      const float* __restrict__ kw_){
  __shared__ __nv_bfloat16 As[2][128][40];
  __shared__ __nv_bfloat16 Bs[2][128][40];
  const int tid = threadIdx.x, lane = tid & 31, warp = tid >> 5;
  const int m0 = blockIdx.y*128, n0 = blockIdx.x*128;
  const int wm = warp >> 1, wn = warp & 1;
  const int m_off = wm*32, n_off = wn*64;

  float c[2][8][4];
  #pragma unroll
  for (int a=0;a<2;a++) for (int b=0;b<8;b++) for (int d=0;d<4;d++) c[a][b][d]=0.f;

  auto load_chunk = [&](int kc, int buf){
    int k0 = kc*32;
    #pragma unroll
    for (int s2=0;s2<2;s2++){
      int s = tid + s2*256;
      int row = s >> 2, c8 = (s & 3) << 3;
      cp_async16(&As[buf][row][c8], g_featsb + (size_t)(m0+row)*HH + k0 + c8);
      cp_async16(&Bs[buf][row][c8], g_wb     + (size_t)(n0+row)*HH + k0 + c8);
    }
    cp_commit();
  };

  load_chunk(0,0);
  for (int kc=0;kc<16;kc++){
    if (kc+1<16) { load_chunk(kc+1,(kc+1)&1); cp_wait<1>(); }
    else         { cp_wait<0>(); }
    __syncthreads();
    const int cur = kc & 1;
    #pragma unroll
    for (int ks=0;ks<2;ks++){
      uint32_t a[2][4];
      #pragma unroll
      for (int mf=0;mf<2;mf++)
        ldsm4(a[mf], &As[cur][m_off + mf*16 + (lane&15)][ks*16 + ((lane>>4)<<3)]);
      uint32_t bb[8][2];
      #pragma unroll
      for (int nf2=0;nf2<4;nf2++){
        uint32_t t[4];
        int nl = n_off + nf2*16 + (lane&7) + (((lane>>4)&1)<<3);
        int kl = ks*16 + (((lane>>3)&1)<<3);
        ldsm4(t, &Bs[cur][nl][kl]);
        bb[nf2*2+0][0]=t[0]; bb[nf2*2+0][1]=t[1];
        bb[nf2*2+1][0]=t[2]; bb[nf2*2+1][1]=t[3];
      }
      #pragma unroll
      for (int mf=0;mf<2;mf++)
        #pragma unroll
        for (int nf=0;nf<8;nf++)
          mma16816(c[mf][nf], a[mf], bb[nf]);
    }
    __syncthreads();
  }
  // epilogue: +bias, store bf16, accumulate q/k partial dots
  float qp[2][2] = {{0.f,0.f},{0.f,0.f}};
  float kp[2][2] = {{0.f,0.f},{0.f,0.f}};
  #pragma unroll
  for (int mf=0;mf<2;mf++){
    #pragma unroll
    for (int nf=0;nf<8;nf++){
      int col = n0 + n_off + nf*8 + ((lane&3)<<1);
      float b0 = __ldg(&fc_b[col]), b1 = __ldg(&fc_b[col+1]);
      float qw0 = __ldg(&qw_[col]), qw1 = __ldg(&qw_[col+1]);
      float kw0 = __ldg(&kw_[col]), kw1 = __ldg(&kw_[col+1]);
      #pragma unroll
      for (int rr=0;rr<2;rr++){
        int row = m0 + m_off + mf*16 + (lane>>2) + rr*8;
        float v0 = c[mf][nf][rr*2+0] + b0;
        float v1 = c[mf][nf][rr*2+1] + b1;
        *reinterpret_cast<__nv_bfloat162*>(&g_fpb[(size_t)row*HH + col]) =
            __floats2bfloat162_rn(v0, v1);
        qp[mf][rr] += v0*qw0 + v1*qw1;
        kp[mf][rr] += v0*kw0 + v1*kw1;
      }
    }
  }
  #pragma unroll
  for (int mf=0;mf<2;mf++){
    #pragma unroll
    for (int rr=0;rr<2;rr++){
      float q = qp[mf][rr], k = kp[mf][rr];
      q += __shfl_xor_sync(0xffffffffu, q, 1);
      q += __shfl_xor_sync(0xffffffffu, q, 2);
      k += __shfl_xor_sync(0xffffffffu, k, 1);
      k += __shfl_xor_sync(0xffffffffu, k, 2);
      if ((lane & 3) == 0){
        int row = m0 + m_off + mf*16 + (lane>>2) + rr*8;
        atomicAdd(&g_qacc[row], q);
        atomicAdd(&g_kacc[row], k);
      }
    }
  }
}

// ---------------- K2: finalize q/k + exp precompute ----------------
__global__ void qk_fin_kernel(const float* __restrict__ qb, const float* __restrict__ kb){
  int i = blockIdx.x*blockDim.x + threadIdx.x;
  if (i < M_TOT){
    float q = g_qacc[i] + __ldg(qb);
    float k = g_kacc[i] + __ldg(kb);
    g_qv[i]=q; g_Eq[i]=expf(q); g_eq[i]=expf(0.01f*q);
    g_kv[i]=k; g_Ek[i]=expf(k); g_ek[i]=expf(0.01f*k);
  }
}

// ---------------- K3: masked-softmax attention + residual ----------------
// R15 + (1) B-fragment software pipeline in the MMA loop,
//       (2) qi/Eqi/eqi hoisted to loop-invariant registers.
#define TJ 64
#define NT (NN/TJ)
#define FPS 520   // fp tile stride (bf16)
#define WSS 72    // w tile stride (bf16): 64 + 8 pad
#define SMEM_K3 (2*TJ*FPS*2 + 2*64*WSS*2 + 3*NN*4 + 4*64*4)

__global__ __launch_bounds__(512,1) void attn_kernel(const float* __restrict__ adj,
                                                     const float* __restrict__ feats,
                                                     float* __restrict__ out){
  extern __shared__ char smraw[];
  __nv_bfloat16* fps = (__nv_bfloat16*)smraw;                          // [2][64][520]
  __nv_bfloat16* ws  = (__nv_bfloat16*)(smraw + 2*TJ*FPS*2);           // [2][64][72]
  float* sk   = (float*)(smraw + 2*TJ*FPS*2 + 2*64*WSS*2);             // [2048]
  float* sE   = sk + NN;
  float* se   = sE + NN;
  float* rq   = se + NN;     // [64]
  float* rEq  = rq + 64;
  float* req  = rEq + 64;
  float* zs   = req + 64;    // [64]

  const int tid = threadIdx.x, lane = tid & 31, warp = tid >> 5;
  const int b  = blockIdx.y;
  const int i0 = blockIdx.x*64;
  const int base = b*NN;

  if (tid < 64){ rq[tid]=g_qv[base+i0+tid]; rEq[tid]=g_Eq[base+i0+tid]; req[tid]=g_eq[base+i0+tid]; }

  const int ii = tid >> 3;           // w-compute / adj row (0..63)
  const int j4 = (tid & 7) << 2;     // w-compute / adj col base
  const float* adjrow = adj + (size_t)(base + i0 + ii)*NN + j4;

  auto load_fp = [&](int jt, int buf){
    const __nv_bfloat16* src = g_fpb + (size_t)(base + jt*TJ)*HH;
    #pragma unroll
    for (int s=0;s<8;s++){
      int seg = tid + s*512;
      int row = seg >> 6, hs = (seg & 63) << 3;
      cp_async16(&fps[(size_t)buf*TJ*FPS + row*FPS + hs], src + (size_t)row*HH + hs);
    }
    cp_commit();
  };

  // adj prefetch registers: this thread's 8 cols of the (jt) tile
  float4 apf[2];
  auto adj_prefetch = [&](int jt){
    const float* p = adjrow + jt*TJ;
    apf[0] = __ldg(reinterpret_cast<const float4*>(p));
    apf[1] = __ldg(reinterpret_cast<const float4*>(p + 32));
  };

  float c[2][8][4];
  #pragma unroll
  for (int a=0;a<2;a++) for (int nb=0;nb<8;nb++) for (int d=0;d<4;d++) c[a][nb][d]=0.f;
  float zp = 0.f;
  const int wm = warp >> 3, wn = warp & 7;
  const int iw = wm*32, hw = wn*64;

  // ---- prologue: stage k-params + fp(0); adj(0) in regs ----
  {
    int seg = tid;  // 0..511
    cp_async16(&sk[seg*4], g_kv + base + seg*4);
    cp_async16(&sE[seg*4], g_Ek + base + seg*4);
    cp_async16(&se[seg*4], g_ek + base + seg*4);
    cp_commit();
  }
  load_fp(0,0);
  adj_prefetch(0);
  cp_wait<0>();
  __syncthreads();               // params + fp(0) visible

  // loop-invariant row params (hoisted out of wcompute)
  const float qi = rq[ii], Eqi = rEq[ii], eqi = req[ii];

  auto wcompute = [&](int jt, int buf){
    #pragma unroll
    for (int half=0; half<2; half++){
      int jj = j4 + half*32;
      int j  = jt*TJ + jj;
      float4 a4 = apf[half];
      float4 k4 = *reinterpret_cast<const float4*>(&sk[j]);
      float4 E4 = *reinterpret_cast<const float4*>(&sE[j]);
      float4 e4 = *reinterpret_cast<const float4*>(&se[j]);
      float w0 = a4.x * ((qi + k4.x >= 0.f) ? Eqi*E4.x : eqi*e4.x);
      float w1 = a4.y * ((qi + k4.y >= 0.f) ? Eqi*E4.y : eqi*e4.y);
      float w2 = a4.z * ((qi + k4.z >= 0.f) ? Eqi*E4.z : eqi*e4.z);
      float w3 = a4.w * ((qi + k4.w >= 0.f) ? Eqi*E4.w : eqi*e4.w);
      zp += (w0 + w1) + (w2 + w3);
      __nv_bfloat16* wrow = &ws[(size_t)buf*64*WSS + ii*WSS + jj];
      *reinterpret_cast<__nv_bfloat162*>(wrow + 0) = __floats2bfloat162_rn(w0, w1);
      *reinterpret_cast<__nv_bfloat162*>(wrow + 2) = __floats2bfloat162_rn(w2, w3);
    }
  };

  wcompute(0,0);                 // uses apf(0), writes ws[0]
  adj_prefetch(1);
  __syncthreads();               // ws(0) visible

  // ---- main loop: one barrier per iteration ----
  for (int jt=0; jt<NT; jt++){
    const int buf = jt & 1;
    const bool more = (jt+1 < NT);
    if (more) load_fp(jt+1, 1-buf);

    // MMA(jt): acc[64x512] += w[64x64] @ fp[64x512]; B-frags software-pipelined
    const __nv_bfloat16* fcur = fps + (size_t)buf*TJ*FPS;
    const __nv_bfloat16* wcur = ws  + (size_t)buf*64*WSS;
    const int klq = (lane&7) + (((lane>>3)&1)<<3);        // k-lane within 16
    const int clq = hw + (((lane>>4)&1)<<3);              // col-lane base
    #pragma unroll
    for (int ks=0;ks<4;ks++){
      uint32_t a[2][4];
      #pragma unroll
      for (int mf=0;mf<2;mf++)
        ldsm4(a[mf], wcur + (size_t)(iw + mf*16 + (lane&15))*WSS + ks*16 + ((lane>>4)<<3));
      uint32_t t0[4], t1[4];
      ldsm4t(t0, fcur + (size_t)(ks*16 + klq)*FPS + clq);          // nfp=0
      #pragma unroll
      for (int nfp=0;nfp<4;nfp++){
        uint32_t* tc = (nfp & 1) ? t1 : t0;
        uint32_t* tn = (nfp & 1) ? t0 : t1;
        if (nfp < 3)
          ldsm4t(tn, fcur + (size_t)(ks*16 + klq)*FPS + clq + (nfp+1)*16);
        #pragma unroll
        for (int mf=0;mf<2;mf++){
          mma16816(c[mf][nfp*2+0], a[mf], tc);
          mma16816(c[mf][nfp*2+1], a[mf], tc+2);
        }
      }
    }

    if (more){
      wcompute(jt+1, 1-buf);     // apf holds adj(jt+1); writes ws[1-buf]
      if (jt+2 < NT) adj_prefetch(jt+2);
      cp_wait<0>();              // fp(jt+1) complete for this thread
    }
    __syncthreads();             // ws(jt+1)+fp(jt+1) visible; all warps done MMA(jt)
  }

  // ---- Z reduction: 8 threads per row ----
  {
    float z = zp;
    z += __shfl_down_sync(0xffffffffu, z, 4, 8);
    z += __shfl_down_sync(0xffffffffu, z, 2, 8);
    z += __shfl_down_sync(0xffffffffu, z, 1, 8);
    if ((lane & 7) == 0) zs[ii] = z;
  }
  __syncthreads();

  // ---- epilogue: /Z + residual ----
  #pragma unroll
  for (int mf=0;mf<2;mf++){
    #pragma unroll
    for (int rr=0;rr<2;rr++){
      int rl = iw + mf*16 + (lane>>2) + rr*8;
      float zinv = 1.0f / zs[rl];
      size_t gro = (size_t)(base + i0 + rl)*HH;
      #pragma unroll
      for (int nf=0;nf<8;nf++){
        int col = hw + nf*8 + ((lane&3)<<1);
        float2 o;
        o.x = c[mf][nf][rr*2+0]*zinv + feats[gro + col + 0];
        o.y = c[mf][nf][rr*2+1]*zinv + feats[gro + col + 1];
        *reinterpret_cast<float2*>(out + gro + col) = o;
      }
    }
  }
}

// ---------------- launch ----------------
extern "C" void kernel_launch(void* const* d_in, const int* in_sizes, int n_in,
                              void* d_out, int out_size){
  const float* feats = (const float*)d_in[0];
  const float* adj   = (const float*)d_in[1];
  const float* fc_w  = (const float*)d_in[2];
  const float* fc_b  = (const float*)d_in[3];
  const float* q_w   = (const float*)d_in[4];
  const float* q_b   = (const float*)d_in[5];
  const float* k_w   = (const float*)d_in[6];
  const float* k_b   = (const float*)d_in[7];
  float* out = (float*)d_out;

  cudaFuncSetAttribute(attn_kernel, cudaFuncAttributeMaxDynamicSharedMemorySize, SMEM_K3);

  // Launch sequence: cvt_all(1), fc_gemm(2), qk_fin(3), attn(4)
  cvt_all_kernel<<<(N4F + 255)/256, 256>>>(feats, fc_w);
  {
    dim3 grid(HH/128, M_TOT/128);
    fc_gemm_kernel<<<grid, 256>>>(fc_b, q_w, k_w);
  }
  qk_fin_kernel<<<(M_TOT+255)/256, 256>>>(q_b, k_b);
  {
    dim3 grid(NN/64, BSZ);
    attn_kernel<<<grid, 512, SMEM_K3>>>(adj, feats, out);
  }
}